// round 14
// baseline (speedup 1.0000x reference)
#include <cuda_runtime.h>
#include <stdint.h>

// MultiIndexSelect: out[to_s[j]] = mat_s[from_s[j]] for s in {0,1,2}, j in [0,L)
// D = 64 floats = 16 float4 = 256 B per row.
//
// FINAL — verified stable across three runs (kernel 80.6-81.5us @ ~6.1 TB/s,
// total 86.1-86.5us):
//  - segment-phased blocks: block-uniform src/from/to pointers; L2 gather
//    working set confined to one 128MB matrix at a time (captures the 1.45x
//    cross-CTA row reuse; measured read traffic ~186MB vs 307MB naive)
//  - 16 lanes per row, one float4 (LDG.E.128) each — plain __ldg is the most
//    efficient L1tex gather path on sm_103 (.cg and evict_last.v8 both
//    regressed via extra L1tex wavefronts)
//  - RPT=4 front-batched payload loads (MLP=4), then streaming stores
//  - streaming .cs stores: output written once, never re-read; keeps the
//    write sweep from evicting the gather set in L2
//  - 64 rows/block, 6250 blocks/segment (exact: L=400000/64), no tails
//
// Converged model (R1-R13): traffic is at the compulsory floor (~493MB) AND
// the ~6.1 TB/s empirical DRAM-efficiency ceiling for random-256B mixed
// read/write is reached simultaneously. Falsified alternatives: persistent
// blocks + index prefetch (R4), L2 evict hints (R8/R11), inverse-permutation
// write sequentialization (R9), deeper software pipeline (R10/R12).

#define D4 16
#define RPT 4
#define ROWS_PER_BLOCK 64
#define BLOCKS_PER_SEG 6250   // L / ROWS_PER_BLOCK

__device__ __forceinline__ void store_streaming(float4* p, float4 v) {
    asm volatile("st.global.cs.v4.f32 [%0], {%1, %2, %3, %4};"
                 :: "l"(p), "f"(v.x), "f"(v.y), "f"(v.z), "f"(v.w) : "memory");
}

__global__ void __launch_bounds__(256)
multi_index_select_kernel(
    const float4* __restrict__ m0,
    const float4* __restrict__ m1,
    const float4* __restrict__ m2,
    const int*    __restrict__ f0,
    const int*    __restrict__ f1,
    const int*    __restrict__ f2,
    const int*    __restrict__ t0,
    const int*    __restrict__ t1,
    const int*    __restrict__ t2,
    float4*       __restrict__ out)
{
    // Block-uniform segment selection (uniform-register pointers, no divergence)
    const int seg = blockIdx.x / BLOCKS_PER_SEG;          // 0, 1, 2
    const int segblk = blockIdx.x - seg * BLOCKS_PER_SEG;

    const float4* __restrict__ src = (seg == 0) ? m0 : (seg == 1) ? m1 : m2;
    const int*    __restrict__ fi  = (seg == 0) ? f0 : (seg == 1) ? f1 : f2;
    const int*    __restrict__ ti  = (seg == 0) ? t0 : (seg == 1) ? t1 : t2;

    const int lane = threadIdx.x & (D4 - 1);              // 0..15
    const int rsub = threadIdx.x >> 4;                    // 0..15
    const int rbase = segblk * ROWS_PER_BLOCK + rsub;     // rows: rbase + 16*i

    // Phase 1: batch all index loads (broadcast within 16-lane row groups)
    int fr[RPT], to[RPT];
    #pragma unroll
    for (int i = 0; i < RPT; i++) {
        int r = rbase + 16 * i;
        fr[i] = __ldg(&fi[r]);
        to[i] = __ldg(&ti[r]);
    }

    // Phase 2: front-batch 4 independent payload loads (MLP=4)
    float4 v[RPT];
    #pragma unroll
    for (int i = 0; i < RPT; i++) {
        v[i] = __ldg(&src[(size_t)fr[i] * D4 + lane]);
    }

    // Phase 3: streaming stores (output written once, never re-read)
    #pragma unroll
    for (int i = 0; i < RPT; i++) {
        store_streaming(&out[(size_t)to[i] * D4 + lane], v[i]);
    }
}

extern "C" void kernel_launch(void* const* d_in, const int* in_sizes, int n_in,
                              void* d_out, int out_size)
{
    const float4* m0 = (const float4*)d_in[0];
    const float4* m1 = (const float4*)d_in[1];
    const float4* m2 = (const float4*)d_in[2];
    const int* f0 = (const int*)d_in[3];
    const int* f1 = (const int*)d_in[4];
    const int* f2 = (const int*)d_in[5];
    const int* t0 = (const int*)d_in[6];
    const int* t1 = (const int*)d_in[7];
    const int* t2 = (const int*)d_in[8];
    float4* out = (float4*)d_out;

    // 3 * 400000 rows / 64 rows per block = 18750 blocks exactly
    multi_index_select_kernel<<<3 * BLOCKS_PER_SEG, 256>>>(
        m0, m1, m2, f0, f1, f2, t0, t1, t2, out);
}

// round 15
// speedup vs baseline: 1.0071x; 1.0071x over previous
#include <cuda_runtime.h>
#include <stdint.h>

// MultiIndexSelect: out[to_s[j]] = mat_s[from_s[j]] for s in {0,1,2}, j in [0,L)
// D = 64 floats = 16 float4 = 256 B per row.
//
// R15 = converged R3/R13 configuration with 512-thread blocks (the one
// structural parameter never varied in isolation): 128 rows/block, RPT=4,
// 3125 blocks/segment (exact: L=400000/128), 9375 blocks total. Fewer CTAs
// -> fewer per-CTA index-phase prologues and wave transitions; byte-level
// behavior identical to the converged kernel.
//
// Converged model (R1-R14): traffic at compulsory floor (~493MB), rate at
// the ~6.1 TB/s empirical ceiling for random-256B mixed R/W. Falsified:
// persistence+prefetch (R4), evict hints (R8/R11), inverse-perm write
// sequentialization (R9), RPT=8 pipeline (R10/R12).

#define D4 16
#define RPT 4
#define THREADS 512
#define ROWS_PER_BLOCK 128    // THREADS/16 * RPT
#define BLOCKS_PER_SEG 3125   // L / ROWS_PER_BLOCK

__device__ __forceinline__ void store_streaming(float4* p, float4 v) {
    asm volatile("st.global.cs.v4.f32 [%0], {%1, %2, %3, %4};"
                 :: "l"(p), "f"(v.x), "f"(v.y), "f"(v.z), "f"(v.w) : "memory");
}

__global__ void __launch_bounds__(THREADS)
multi_index_select_kernel(
    const float4* __restrict__ m0,
    const float4* __restrict__ m1,
    const float4* __restrict__ m2,
    const int*    __restrict__ f0,
    const int*    __restrict__ f1,
    const int*    __restrict__ f2,
    const int*    __restrict__ t0,
    const int*    __restrict__ t1,
    const int*    __restrict__ t2,
    float4*       __restrict__ out)
{
    // Block-uniform segment selection (uniform-register pointers, no divergence)
    const int seg = blockIdx.x / BLOCKS_PER_SEG;          // 0, 1, 2
    const int segblk = blockIdx.x - seg * BLOCKS_PER_SEG;

    const float4* __restrict__ src = (seg == 0) ? m0 : (seg == 1) ? m1 : m2;
    const int*    __restrict__ fi  = (seg == 0) ? f0 : (seg == 1) ? f1 : f2;
    const int*    __restrict__ ti  = (seg == 0) ? t0 : (seg == 1) ? t1 : t2;

    const int lane = threadIdx.x & (D4 - 1);              // 0..15
    const int rsub = threadIdx.x >> 4;                    // 0..31
    const int rbase = segblk * ROWS_PER_BLOCK + rsub;     // rows: rbase + 32*i

    // Phase 1: batch all index loads (broadcast within 16-lane row groups)
    int fr[RPT], to[RPT];
    #pragma unroll
    for (int i = 0; i < RPT; i++) {
        int r = rbase + 32 * i;
        fr[i] = __ldg(&fi[r]);
        to[i] = __ldg(&ti[r]);
    }

    // Phase 2: front-batch 4 independent payload loads (MLP=4)
    float4 v[RPT];
    #pragma unroll
    for (int i = 0; i < RPT; i++) {
        v[i] = __ldg(&src[(size_t)fr[i] * D4 + lane]);
    }

    // Phase 3: streaming stores (output written once, never re-read)
    #pragma unroll
    for (int i = 0; i < RPT; i++) {
        store_streaming(&out[(size_t)to[i] * D4 + lane], v[i]);
    }
}

extern "C" void kernel_launch(void* const* d_in, const int* in_sizes, int n_in,
                              void* d_out, int out_size)
{
    const float4* m0 = (const float4*)d_in[0];
    const float4* m1 = (const float4*)d_in[1];
    const float4* m2 = (const float4*)d_in[2];
    const int* f0 = (const int*)d_in[3];
    const int* f1 = (const int*)d_in[4];
    const int* f2 = (const int*)d_in[5];
    const int* t0 = (const int*)d_in[6];
    const int* t1 = (const int*)d_in[7];
    const int* t2 = (const int*)d_in[8];
    float4* out = (float4*)d_out;

    // 3 * 400000 rows / 128 rows per block = 9375 blocks exactly
    multi_index_select_kernel<<<3 * BLOCKS_PER_SEG, THREADS>>>(
        m0, m1, m2, f0, f1, f2, t0, t1, t2, out);
}